// round 5
// baseline (speedup 1.0000x reference)
#include <cuda_runtime.h>
#include <math.h>
#include <float.h>

// Problem constants
#define SEQ 4096
#define DM  512
#define FF  2048
#define NH  8
#define DH  64

// ---------------- scratch (allocation-free: __device__ globals) ----------------
__device__ float g_q[SEQ * DM];
__device__ float g_k[SEQ * DM];
__device__ float g_v[SEQ * DM];
__device__ float g_attn[SEQ * DM];
__device__ float g_tmp[SEQ * DM];
__device__ float g_y[SEQ * DM];
__device__ float g_h[SEQ * FF];

// ---------------- SGEMM: C[M,N] = A[M,K] @ B[K,N] + bias, optional ReLU --------
// BM=BN=128, BK=16, 256 threads, 8x8 microtile. All dims divisible (M=4096,
// N in {512,2048}, K in {512,2048}).
template <bool RELU>
__global__ __launch_bounds__(256)
void sgemm_bias(const float* __restrict__ A, const float* __restrict__ B,
                const float* __restrict__ bias, float* __restrict__ C,
                int M, int N, int K)
{
    __shared__ float As[16][128];
    __shared__ float Bs[16][128];

    const int tid = threadIdx.x;
    const int m0 = blockIdx.y * 128;
    const int n0 = blockIdx.x * 128;
    const int tr = tid >> 4;   // 0..15 -> rows tr*8..tr*8+7
    const int tc = tid & 15;   // 0..15 -> cols tc*8..tc*8+7

    float acc[8][8];
#pragma unroll
    for (int i = 0; i < 8; ++i)
#pragma unroll
        for (int j = 0; j < 8; ++j) acc[i][j] = 0.f;

    for (int k0 = 0; k0 < K; k0 += 16) {
#pragma unroll
        for (int l = 0; l < 2; ++l) {
            int idx = tid + l * 256;          // 0..511
            int ra = idx >> 2, ca = idx & 3;  // A tile: 128 rows x 4 float4
            float4 av = *(const float4*)(A + (size_t)(m0 + ra) * K + k0 + ca * 4);
            As[ca * 4 + 0][ra] = av.x;
            As[ca * 4 + 1][ra] = av.y;
            As[ca * 4 + 2][ra] = av.z;
            As[ca * 4 + 3][ra] = av.w;
            int rb = idx >> 5, cb = idx & 31; // B tile: 16 rows x 32 float4
            *(float4*)(&Bs[rb][cb * 4]) =
                *(const float4*)(B + (size_t)(k0 + rb) * N + n0 + cb * 4);
        }
        __syncthreads();

#pragma unroll
        for (int kk = 0; kk < 16; ++kk) {
            float ra[8], rb[8];
            *(float4*)(ra + 0) = *(const float4*)(&As[kk][tr * 8 + 0]);
            *(float4*)(ra + 4) = *(const float4*)(&As[kk][tr * 8 + 4]);
            *(float4*)(rb + 0) = *(const float4*)(&Bs[kk][tc * 8 + 0]);
            *(float4*)(rb + 4) = *(const float4*)(&Bs[kk][tc * 8 + 4]);
#pragma unroll
            for (int i = 0; i < 8; ++i)
#pragma unroll
                for (int j = 0; j < 8; ++j)
                    acc[i][j] += ra[i] * rb[j];
        }
        __syncthreads();
    }

#pragma unroll
    for (int i = 0; i < 8; ++i) {
        int m = m0 + tr * 8 + i;
#pragma unroll
        for (int j4 = 0; j4 < 2; ++j4) {
            int n = n0 + tc * 8 + j4 * 4;
            float4 bb = *(const float4*)(bias + n);
            float4 o;
            o.x = acc[i][j4 * 4 + 0] + bb.x;
            o.y = acc[i][j4 * 4 + 1] + bb.y;
            o.z = acc[i][j4 * 4 + 2] + bb.z;
            o.w = acc[i][j4 * 4 + 3] + bb.w;
            if (RELU) {
                o.x = fmaxf(o.x, 0.f); o.y = fmaxf(o.y, 0.f);
                o.z = fmaxf(o.z, 0.f); o.w = fmaxf(o.w, 0.f);
            }
            *(float4*)(C + (size_t)m * N + n) = o;
        }
    }
}

// ---------------- Flash attention, fp32, online softmax ----------------------
// grid (SEQ/64, NH), 256 threads. BQ=BKV=64, Dh=64.
// thread (tr,tc): score microtile rows i = tr*4+r, cols j = tc + 16*c.
// acc dims d = tc*4 + c.  Smem stride 68 floats (17 float4, odd) for banks.
// sP aliases sK (K tile is dead once scores are computed); one extra
// __syncthreads() separates the read and overwrite phases. 3 buffers = 52 KB,
// so 4 CTAs/SM co-reside (vs 3 with a separate sP buffer).
#define SSTR 68
__global__ __launch_bounds__(256)
void attn_kernel(const float* __restrict__ Q, const float* __restrict__ Kg,
                 const float* __restrict__ Vg, const int* __restrict__ mask,
                 float* __restrict__ O)
{
    const int head = blockIdx.y;
    const int q0 = blockIdx.x * 64;
    const int tid = threadIdx.x;
    const int tr = tid >> 4;
    const int tc = tid & 15;

    extern __shared__ float sm[];
    float* sQ = sm;
    float* sK = sm + 64 * SSTR;
    float* sV = sm + 2 * 64 * SSTR;
    float* sP = sK;   // alias: K tile is dead after the score phase

    // load Q tile (once per block)
#pragma unroll
    for (int l = 0; l < 4; ++l) {
        int idx = tid + l * 256;
        int r = idx >> 4, c4 = idx & 15;
        *(float4*)(sQ + r * SSTR + c4 * 4) =
            *(const float4*)(Q + (size_t)(q0 + r) * DM + head * DH + c4 * 4);
    }

    float mrow[4], lrow[4], acc[4][4];
#pragma unroll
    for (int r = 0; r < 4; ++r) {
        mrow[r] = -3.0e38f;
        lrow[r] = 0.f;
#pragma unroll
        for (int c = 0; c < 4; ++c) acc[r][c] = 0.f;
    }

    for (int k0 = 0; k0 < SEQ; k0 += 64) {
#pragma unroll
        for (int l = 0; l < 4; ++l) {
            int idx = tid + l * 256;
            int r = idx >> 4, c4 = idx & 15;
            *(float4*)(sK + r * SSTR + c4 * 4) =
                *(const float4*)(Kg + (size_t)(k0 + r) * DM + head * DH + c4 * 4);
            *(float4*)(sV + r * SSTR + c4 * 4) =
                *(const float4*)(Vg + (size_t)(k0 + r) * DM + head * DH + c4 * 4);
        }
        __syncthreads();

        // ---- scores s[r][c] = q_i . k_j ----
        float s[4][4];
#pragma unroll
        for (int r = 0; r < 4; ++r)
#pragma unroll
            for (int c = 0; c < 4; ++c) s[r][c] = 0.f;

#pragma unroll
        for (int d = 0; d < DH; d += 4) {
            float4 qv[4], kv[4];
#pragma unroll
            for (int r = 0; r < 4; ++r)
                qv[r] = *(const float4*)(sQ + (tr * 4 + r) * SSTR + d);
#pragma unroll
            for (int c = 0; c < 4; ++c)
                kv[c] = *(const float4*)(sK + (tc + 16 * c) * SSTR + d);
#pragma unroll
            for (int r = 0; r < 4; ++r)
#pragma unroll
                for (int c = 0; c < 4; ++c)
                    s[r][c] += qv[r].x * kv[c].x + qv[r].y * kv[c].y +
                               qv[r].z * kv[c].z + qv[r].w * kv[c].w;
        }

        // ---- mask ----
#pragma unroll
        for (int r = 0; r < 4; ++r) {
            const int* mp = mask + (size_t)(q0 + tr * 4 + r) * SEQ + k0;
#pragma unroll
            for (int c = 0; c < 4; ++c)
                if (mp[tc + 16 * c] == 0) s[r][c] = -1.0e9f;
        }

        // all score reads of sK are done before sP (=sK) is overwritten
        __syncthreads();

        // ---- online softmax (per row, reduce across the 16 tc lanes) ----
#pragma unroll
        for (int r = 0; r < 4; ++r) {
            float tm = fmaxf(fmaxf(s[r][0], s[r][1]), fmaxf(s[r][2], s[r][3]));
#pragma unroll
            for (int off = 8; off >= 1; off >>= 1)
                tm = fmaxf(tm, __shfl_xor_sync(0xffffffffu, tm, off));
            float nm = fmaxf(mrow[r], tm);
            float sc = __expf(mrow[r] - nm);
            mrow[r] = nm;
            float rs = 0.f;
#pragma unroll
            for (int c = 0; c < 4; ++c) {
                float p = __expf(s[r][c] - nm);
                rs += p;
                sP[(tr * 4 + r) * SSTR + tc + 16 * c] = p;
            }
#pragma unroll
            for (int off = 8; off >= 1; off >>= 1)
                rs += __shfl_xor_sync(0xffffffffu, rs, off);
            lrow[r] = lrow[r] * sc + rs;
#pragma unroll
            for (int c = 0; c < 4; ++c) acc[r][c] *= sc;
        }
        __syncthreads();

        // ---- acc += P @ V  (acc dims d = tc*4 + c) ----
#pragma unroll 8
        for (int j = 0; j < 64; ++j) {
            float4 vv = *(const float4*)(sV + j * SSTR + tc * 4);
#pragma unroll
            for (int r = 0; r < 4; ++r) {
                float p = sP[(tr * 4 + r) * SSTR + j];
                acc[r][0] += p * vv.x;
                acc[r][1] += p * vv.y;
                acc[r][2] += p * vv.z;
                acc[r][3] += p * vv.w;
            }
        }
        __syncthreads();
    }

#pragma unroll
    for (int r = 0; r < 4; ++r) {
        float inv = 1.f / lrow[r];
        float4 o = make_float4(acc[r][0] * inv, acc[r][1] * inv,
                               acc[r][2] * inv, acc[r][3] * inv);
        *(float4*)(O + (size_t)(q0 + tr * 4 + r) * DM + head * DH + tc * 4) = o;
    }
}

// ---------------- residual + LayerNorm: out = LN(X + R) * g + b --------------
// one block per row (512 elements), 256 threads, 2 elements each.
__global__ __launch_bounds__(256)
void ln_res_kernel(const float* __restrict__ X, const float* __restrict__ R,
                   const float* __restrict__ g, const float* __restrict__ b,
                   float* __restrict__ out)
{
    __shared__ float red[8];
    __shared__ float stat[2];
    const int row = blockIdx.x;
    const int tid = threadIdx.x;
    const int col = tid * 2;

    float2 xv = *(const float2*)(X + (size_t)row * DM + col);
    float2 rv = *(const float2*)(R + (size_t)row * DM + col);
    float a0 = xv.x + rv.x;
    float a1 = xv.y + rv.y;

    float s = a0 + a1;
#pragma unroll
    for (int off = 16; off >= 1; off >>= 1)
        s += __shfl_xor_sync(0xffffffffu, s, off);
    if ((tid & 31) == 0) red[tid >> 5] = s;
    __syncthreads();
    if (tid == 0) {
        float t = 0.f;
#pragma unroll
        for (int i = 0; i < 8; ++i) t += red[i];
        stat[0] = t * (1.f / (float)DM);
    }
    __syncthreads();
    const float mean = stat[0];

    float d0 = a0 - mean, d1 = a1 - mean;
    float sq = d0 * d0 + d1 * d1;
#pragma unroll
    for (int off = 16; off >= 1; off >>= 1)
        sq += __shfl_xor_sync(0xffffffffu, sq, off);
    if ((tid & 31) == 0) red[tid >> 5] = sq;
    __syncthreads();
    if (tid == 0) {
        float t = 0.f;
#pragma unroll
        for (int i = 0; i < 8; ++i) t += red[i];
        stat[1] = t * (1.f / (float)DM);
    }
    __syncthreads();
    const float rstd = rsqrtf(stat[1] + 1e-5f);

    float2 gv = *(const float2*)(g + col);
    float2 bv = *(const float2*)(b + col);
    float2 o;
    o.x = d0 * rstd * gv.x + bv.x;
    o.y = d1 * rstd * gv.y + bv.y;
    *(float2*)(out + (size_t)row * DM + col) = o;
}

// ---------------- launch ------------------------------------------------------
extern "C" void kernel_launch(void* const* d_in, const int* in_sizes, int n_in,
                              void* d_out, int out_size)
{
    (void)in_sizes; (void)n_in; (void)out_size;

    const float* x   = (const float*)d_in[0];
    const int*   msk = (const int*)  d_in[1];
    const float* wq  = (const float*)d_in[2];
    const float* bq  = (const float*)d_in[3];
    const float* wk  = (const float*)d_in[4];
    const float* bk  = (const float*)d_in[5];
    const float* wv  = (const float*)d_in[6];
    const float* bv  = (const float*)d_in[7];
    const float* wo  = (const float*)d_in[8];
    const float* bo  = (const float*)d_in[9];
    const float* w1  = (const float*)d_in[10];
    const float* b1  = (const float*)d_in[11];
    const float* w2  = (const float*)d_in[12];
    const float* b2  = (const float*)d_in[13];
    const float* g1  = (const float*)d_in[14];
    const float* be1 = (const float*)d_in[15];
    const float* g2  = (const float*)d_in[16];
    const float* be2 = (const float*)d_in[17];
    float* out = (float*)d_out;

    float *q, *k, *v, *attn, *tmp, *y, *h;
    cudaGetSymbolAddress((void**)&q,    g_q);
    cudaGetSymbolAddress((void**)&k,    g_k);
    cudaGetSymbolAddress((void**)&v,    g_v);
    cudaGetSymbolAddress((void**)&attn, g_attn);
    cudaGetSymbolAddress((void**)&tmp,  g_tmp);
    cudaGetSymbolAddress((void**)&y,    g_y);
    cudaGetSymbolAddress((void**)&h,    g_h);

    const dim3 blk(256);

    // Q/K/V projections
    sgemm_bias<false><<<dim3(DM / 128, SEQ / 128), blk>>>(x, wq, bq, q, SEQ, DM, DM);
    sgemm_bias<false><<<dim3(DM / 128, SEQ / 128), blk>>>(x, wk, bk, k, SEQ, DM, DM);
    sgemm_bias<false><<<dim3(DM / 128, SEQ / 128), blk>>>(x, wv, bv, v, SEQ, DM, DM);

    // attention (3 smem buffers of 64*SSTR floats: Q, K/P, V)
    const int smem = 3 * 64 * SSTR * (int)sizeof(float);
    cudaFuncSetAttribute(attn_kernel, cudaFuncAttributeMaxDynamicSharedMemorySize, smem);
    attn_kernel<<<dim3(SEQ / 64, NH), blk, smem>>>(q, k, v, msk, attn);

    // output projection + residual + LN1
    sgemm_bias<false><<<dim3(DM / 128, SEQ / 128), blk>>>(attn, wo, bo, tmp, SEQ, DM, DM);
    ln_res_kernel<<<SEQ, blk>>>(x, tmp, g1, be1, y);

    // FFN
    sgemm_bias<true ><<<dim3(FF / 128, SEQ / 128), blk>>>(y, w1, b1, h, SEQ, FF, DM);
    sgemm_bias<false><<<dim3(DM / 128, SEQ / 128), blk>>>(h, w2, b2, tmp, SEQ, DM, FF);
    ln_res_kernel<<<SEQ, blk>>>(y, tmp, g2, be2, out);
}

// round 8
// speedup vs baseline: 1.0702x; 1.0702x over previous
#include <cuda_runtime.h>
#include <math.h>
#include <float.h>

// Problem constants
#define SEQ 4096
#define DM  512
#define FF  2048
#define NH  8
#define DH  64

// ---------------- scratch (allocation-free: __device__ globals) ----------------
__device__ float g_q[SEQ * DM];
__device__ float g_k[SEQ * DM];
__device__ float g_v[SEQ * DM];
__device__ float g_attn[SEQ * DM];
__device__ float g_tmp[SEQ * DM];
__device__ float g_y[SEQ * DM];
__device__ float g_h[SEQ * FF];

// ---------------- packed f32x2 FMA (Blackwell FFMA2, PTX-only) ----------------
union f2u { float2 f; unsigned long long u; };

__device__ __forceinline__ float2 ffma2(float2 a, float2 b, float2 c)
{
    f2u A, B, C, D;
    A.f = a; B.f = b; C.f = c;
    asm("fma.rn.f32x2 %0, %1, %2, %3;" : "=l"(D.u) : "l"(A.u), "l"(B.u), "l"(C.u));
    return D.f;
}

// ---------------- SGEMM core: C[M,N] = A[M,K] @ B[K,N] + bias, opt ReLU -------
// BM=BN=128, BK=16, 256 threads, 8x8 microtile (acc as float2[8][4], FFMA2).
template <bool RELU>
__device__ __forceinline__
void sgemm_body(const float* __restrict__ A, const float* __restrict__ B,
                const float* __restrict__ bias, float* __restrict__ C,
                int N, int K, int m0, int n0)
{
    __shared__ float As[16][128];
    __shared__ float Bs[16][128];

    const int tid = threadIdx.x;
    const int tr = tid >> 4;   // 0..15 -> rows tr*8..tr*8+7
    const int tc = tid & 15;   // 0..15 -> cols tc*8..tc*8+7

    float2 acc[8][4];
#pragma unroll
    for (int i = 0; i < 8; ++i)
#pragma unroll
        for (int j = 0; j < 4; ++j) acc[i][j] = make_float2(0.f, 0.f);

    for (int k0 = 0; k0 < K; k0 += 16) {
#pragma unroll
        for (int l = 0; l < 2; ++l) {
            int idx = tid + l * 256;          // 0..511
            int ra = idx >> 2, ca = idx & 3;  // A tile: 128 rows x 4 float4
            float4 av = *(const float4*)(A + (size_t)(m0 + ra) * K + k0 + ca * 4);
            As[ca * 4 + 0][ra] = av.x;
            As[ca * 4 + 1][ra] = av.y;
            As[ca * 4 + 2][ra] = av.z;
            As[ca * 4 + 3][ra] = av.w;
            int rb = idx >> 5, cb = idx & 31; // B tile: 16 rows x 32 float4
            *(float4*)(&Bs[rb][cb * 4]) =
                *(const float4*)(B + (size_t)(k0 + rb) * N + n0 + cb * 4);
        }
        __syncthreads();

#pragma unroll
        for (int kk = 0; kk < 16; ++kk) {
            float ra[8];
            *(float4*)(ra + 0) = *(const float4*)(&As[kk][tr * 8 + 0]);
            *(float4*)(ra + 4) = *(const float4*)(&As[kk][tr * 8 + 4]);
            float4 b0 = *(const float4*)(&Bs[kk][tc * 8 + 0]);
            float4 b1 = *(const float4*)(&Bs[kk][tc * 8 + 4]);
            float2 rb[4];
            rb[0] = make_float2(b0.x, b0.y);
            rb[1] = make_float2(b0.z, b0.w);
            rb[2] = make_float2(b1.x, b1.y);
            rb[3] = make_float2(b1.z, b1.w);
#pragma unroll
            for (int i = 0; i < 8; ++i) {
                float2 aa = make_float2(ra[i], ra[i]);
#pragma unroll
                for (int j = 0; j < 4; ++j)
                    acc[i][j] = ffma2(aa, rb[j], acc[i][j]);
            }
        }
        __syncthreads();
    }

#pragma unroll
    for (int i = 0; i < 8; ++i) {
        int m = m0 + tr * 8 + i;
#pragma unroll
        for (int j4 = 0; j4 < 2; ++j4) {
            int n = n0 + tc * 8 + j4 * 4;
            float4 bb = *(const float4*)(bias + n);
            float4 o;
            o.x = acc[i][j4 * 2 + 0].x + bb.x;
            o.y = acc[i][j4 * 2 + 0].y + bb.y;
            o.z = acc[i][j4 * 2 + 1].x + bb.z;
            o.w = acc[i][j4 * 2 + 1].y + bb.w;
            if (RELU) {
                o.x = fmaxf(o.x, 0.f); o.y = fmaxf(o.y, 0.f);
                o.z = fmaxf(o.z, 0.f); o.w = fmaxf(o.w, 0.f);
            }
            *(float4*)(C + (size_t)m * N + n) = o;
        }
    }
}

template <bool RELU>
__global__ __launch_bounds__(256)
void sgemm_bias(const float* __restrict__ A, const float* __restrict__ B,
                const float* __restrict__ bias, float* __restrict__ C,
                int N, int K)
{
    sgemm_body<RELU>(A, B, bias, C, N, K, blockIdx.y * 128, blockIdx.x * 128);
}

// Fused Q/K/V projection: blockIdx.z selects which of the three GEMMs.
// 384 CTAs total (vs 3 x 128) -> full-chip waves, fewer launch tails.
__global__ __launch_bounds__(256)
void qkv_gemm(const float* __restrict__ X,
              const float* __restrict__ Wq, const float* __restrict__ Bq, float* __restrict__ Oq,
              const float* __restrict__ Wk, const float* __restrict__ Bk, float* __restrict__ Ok,
              const float* __restrict__ Wv, const float* __restrict__ Bv, float* __restrict__ Ov)
{
    const float* W; const float* Bb; float* O;
    if (blockIdx.z == 0)      { W = Wq; Bb = Bq; O = Oq; }
    else if (blockIdx.z == 1) { W = Wk; Bb = Bk; O = Ok; }
    else                      { W = Wv; Bb = Bv; O = Ov; }
    sgemm_body<false>(X, W, Bb, O, DM, DM, blockIdx.y * 128, blockIdx.x * 128);
}

// ---------------- Flash attention, fp32, online softmax ----------------------
// grid (SEQ/64, NH), 256 threads. BQ=BKV=64, Dh=64.
// thread (tr,tc): score microtile rows i = tr*4+r, cols j = tc + 16*c.
// acc dims d = tc*4 + c.  Smem stride 68 floats (17 float4, odd) for banks.
// sP aliases sK (K tile dead after score phase; extra sync separates phases).
// Inner products use FFMA2. Mask is prefetched into registers before the
// score phase so its LDG latency hides under the FFMA2 work.
#define SSTR 68
__global__ __launch_bounds__(256)
void attn_kernel(const float* __restrict__ Q, const float* __restrict__ Kg,
                 const float* __restrict__ Vg, const int* __restrict__ mask,
                 float* __restrict__ O)
{
    const int head = blockIdx.y;
    const int q0 = blockIdx.x * 64;
    const int tid = threadIdx.x;
    const int tr = tid >> 4;
    const int tc = tid & 15;

    extern __shared__ float sm[];
    float* sQ = sm;
    float* sK = sm + 64 * SSTR;
    float* sV = sm + 2 * 64 * SSTR;
    float* sP = sK;   // alias: K tile is dead after the score phase

    // load Q tile (once per block)
#pragma unroll
    for (int l = 0; l < 4; ++l) {
        int idx = tid + l * 256;
        int r = idx >> 4, c4 = idx & 15;
        *(float4*)(sQ + r * SSTR + c4 * 4) =
            *(const float4*)(Q + (size_t)(q0 + r) * DM + head * DH + c4 * 4);
    }

    float mrow[4], lrow[4];
    float2 acc2[4][2];
#pragma unroll
    for (int r = 0; r < 4; ++r) {
        mrow[r] = -3.0e38f;
        lrow[r] = 0.f;
        acc2[r][0] = make_float2(0.f, 0.f);
        acc2[r][1] = make_float2(0.f, 0.f);
    }

    for (int k0 = 0; k0 < SEQ; k0 += 64) {
        // ---- prefetch mask bits for this tile (LDG latency hides under
        //      the K/V tile load + score compute) ----
        int mreg[4][4];
#pragma unroll
        for (int r = 0; r < 4; ++r) {
            const int* mp = mask + (size_t)(q0 + tr * 4 + r) * SEQ + k0;
#pragma unroll
            for (int c = 0; c < 4; ++c)
                mreg[r][c] = __ldg(mp + tc + 16 * c);
        }

#pragma unroll
        for (int l = 0; l < 4; ++l) {
            int idx = tid + l * 256;
            int r = idx >> 4, c4 = idx & 15;
            *(float4*)(sK + r * SSTR + c4 * 4) =
                *(const float4*)(Kg + (size_t)(k0 + r) * DM + head * DH + c4 * 4);
            *(float4*)(sV + r * SSTR + c4 * 4) =
                *(const float4*)(Vg + (size_t)(k0 + r) * DM + head * DH + c4 * 4);
        }
        __syncthreads();

        // ---- scores: pairwise float2 accumulation, FFMA2 ----
        float2 s2[4][4];
#pragma unroll
        for (int r = 0; r < 4; ++r)
#pragma unroll
            for (int c = 0; c < 4; ++c) s2[r][c] = make_float2(0.f, 0.f);

#pragma unroll
        for (int d = 0; d < DH; d += 4) {
            float4 qv[4], kv[4];
#pragma unroll
            for (int r = 0; r < 4; ++r)
                qv[r] = *(const float4*)(sQ + (tr * 4 + r) * SSTR + d);
#pragma unroll
            for (int c = 0; c < 4; ++c)
                kv[c] = *(const float4*)(sK + (tc + 16 * c) * SSTR + d);
#pragma unroll
            for (int r = 0; r < 4; ++r) {
                float2 q01 = make_float2(qv[r].x, qv[r].y);
                float2 q23 = make_float2(qv[r].z, qv[r].w);
#pragma unroll
                for (int c = 0; c < 4; ++c) {
                    s2[r][c] = ffma2(q01, make_float2(kv[c].x, kv[c].y), s2[r][c]);
                    s2[r][c] = ffma2(q23, make_float2(kv[c].z, kv[c].w), s2[r][c]);
                }
            }
        }

        float s[4][4];
#pragma unroll
        for (int r = 0; r < 4; ++r)
#pragma unroll
            for (int c = 0; c < 4; ++c) {
                s[r][c] = s2[r][c].x + s2[r][c].y;
                if (mreg[r][c] == 0) s[r][c] = -1.0e9f;
            }

        // all score reads of sK done before sP (=sK) is overwritten
        __syncthreads();

        // ---- online softmax (per row, reduce across the 16 tc lanes) ----
#pragma unroll
        for (int r = 0; r < 4; ++r) {
            float tm = fmaxf(fmaxf(s[r][0], s[r][1]), fmaxf(s[r][2], s[r][3]));
#pragma unroll
            for (int off = 8; off >= 1; off >>= 1)
                tm = fmaxf(tm, __shfl_xor_sync(0xffffffffu, tm, off));
            float nm = fmaxf(mrow[r], tm);
            float sc = __expf(mrow[r] - nm);
            mrow[r] = nm;
            float rs = 0.f;
#pragma unroll
            for (int c = 0; c < 4; ++c) {
                float p = __expf(s[r][c] - nm);
                rs += p;
                sP[(tr * 4 + r) * SSTR + tc + 16 * c] = p;
            }
#pragma unroll
            for (int off = 8; off >= 1; off >>= 1)
                rs += __shfl_xor_sync(0xffffffffu, rs, off);
            lrow[r] = lrow[r] * sc + rs;
            acc2[r][0].x *= sc; acc2[r][0].y *= sc;
            acc2[r][1].x *= sc; acc2[r][1].y *= sc;
        }
        __syncthreads();

        // ---- acc += P @ V  (acc dims d = tc*4 + {0..3}), FFMA2 ----
#pragma unroll 8
        for (int j = 0; j < 64; ++j) {
            float4 vv = *(const float4*)(sV + j * SSTR + tc * 4);
            float2 v0 = make_float2(vv.x, vv.y);
            float2 v1 = make_float2(vv.z, vv.w);
#pragma unroll
            for (int r = 0; r < 4; ++r) {
                float p = sP[(tr * 4 + r) * SSTR + j];
                float2 pp = make_float2(p, p);
                acc2[r][0] = ffma2(pp, v0, acc2[r][0]);
                acc2[r][1] = ffma2(pp, v1, acc2[r][1]);
            }
        }
        __syncthreads();
    }

#pragma unroll
    for (int r = 0; r < 4; ++r) {
        float inv = 1.f / lrow[r];
        float4 o = make_float4(acc2[r][0].x * inv, acc2[r][0].y * inv,
                               acc2[r][1].x * inv, acc2[r][1].y * inv);
        *(float4*)(O + (size_t)(q0 + tr * 4 + r) * DM + head * DH + tc * 4) = o;
    }
}

// ---------------- residual + LayerNorm: out = LN(X + R) * g + b --------------
// one block per row (512 elements), 256 threads, 2 elements each.
__global__ __launch_bounds__(256)
void ln_res_kernel(const float* __restrict__ X, const float* __restrict__ R,
                   const float* __restrict__ g, const float* __restrict__ b,
                   float* __restrict__ out)
{
    __shared__ float red[8];
    __shared__ float stat[2];
    const int row = blockIdx.x;
    const int tid = threadIdx.x;
    const int col = tid * 2;

    float2 xv = *(const float2*)(X + (size_t)row * DM + col);
    float2 rv = *(const float2*)(R + (size_t)row * DM + col);
    float a0 = xv.x + rv.x;
    float a1 = xv.y + rv.y;

    float s = a0 + a1;
#pragma unroll
    for (int off = 16; off >= 1; off >>= 1)
        s += __shfl_xor_sync(0xffffffffu, s, off);
    if ((tid & 31) == 0) red[tid >> 5] = s;
    __syncthreads();
    if (tid == 0) {
        float t = 0.f;
#pragma unroll
        for (int i = 0; i < 8; ++i) t += red[i];
        stat[0] = t * (1.f / (float)DM);
    }
    __syncthreads();
    const float mean = stat[0];

    float d0 = a0 - mean, d1 = a1 - mean;
    float sq = d0 * d0 + d1 * d1;
#pragma unroll
    for (int off = 16; off >= 1; off >>= 1)
        sq += __shfl_xor_sync(0xffffffffu, sq, off);
    if ((tid & 31) == 0) red[tid >> 5] = sq;
    __syncthreads();
    if (tid == 0) {
        float t = 0.f;
#pragma unroll
        for (int i = 0; i < 8; ++i) t += red[i];
        stat[1] = t * (1.f / (float)DM);
    }
    __syncthreads();
    const float rstd = rsqrtf(stat[1] + 1e-5f);

    float2 gv = *(const float2*)(g + col);
    float2 bv = *(const float2*)(b + col);
    float2 o;
    o.x = d0 * rstd * gv.x + bv.x;
    o.y = d1 * rstd * gv.y + bv.y;
    *(float2*)(out + (size_t)row * DM + col) = o;
}

// ---------------- launch ------------------------------------------------------
extern "C" void kernel_launch(void* const* d_in, const int* in_sizes, int n_in,
                              void* d_out, int out_size)
{
    (void)in_sizes; (void)n_in; (void)out_size;

    const float* x   = (const float*)d_in[0];
    const int*   msk = (const int*)  d_in[1];
    const float* wq  = (const float*)d_in[2];
    const float* bq  = (const float*)d_in[3];
    const float* wk  = (const float*)d_in[4];
    const float* bk  = (const float*)d_in[5];
    const float* wv  = (const float*)d_in[6];
    const float* bv  = (const float*)d_in[7];
    const float* wo  = (const float*)d_in[8];
    const float* bo  = (const float*)d_in[9];
    const float* w1  = (const float*)d_in[10];
    const float* b1  = (const float*)d_in[11];
    const float* w2  = (const float*)d_in[12];
    const float* b2  = (const float*)d_in[13];
    const float* g1  = (const float*)d_in[14];
    const float* be1 = (const float*)d_in[15];
    const float* g2  = (const float*)d_in[16];
    const float* be2 = (const float*)d_in[17];
    float* out = (float*)d_out;

    float *q, *k, *v, *attn, *tmp, *y, *h;
    cudaGetSymbolAddress((void**)&q,    g_q);
    cudaGetSymbolAddress((void**)&k,    g_k);
    cudaGetSymbolAddress((void**)&v,    g_v);
    cudaGetSymbolAddress((void**)&attn, g_attn);
    cudaGetSymbolAddress((void**)&tmp,  g_tmp);
    cudaGetSymbolAddress((void**)&y,    g_y);
    cudaGetSymbolAddress((void**)&h,    g_h);

    const dim3 blk(256);

    // Q/K/V projections fused into one launch (grid.z picks the GEMM)
    qkv_gemm<<<dim3(DM / 128, SEQ / 128, 3), blk>>>(
        x, wq, bq, q, wk, bk, k, wv, bv, v);

    // attention (3 smem buffers of 64*SSTR floats: Q, K/P, V)
    const int smem = 3 * 64 * SSTR * (int)sizeof(float);
    cudaFuncSetAttribute(attn_kernel, cudaFuncAttributeMaxDynamicSharedMemorySize, smem);
    attn_kernel<<<dim3(SEQ / 64, NH), blk, smem>>>(q, k, v, msk, attn);

    // output projection + residual + LN1
    sgemm_bias<false><<<dim3(DM / 128, SEQ / 128), blk>>>(attn, wo, bo, tmp, DM, DM);
    ln_res_kernel<<<SEQ, blk>>>(x, tmp, g1, be1, y);

    // FFN
    sgemm_bias<true ><<<dim3(FF / 128, SEQ / 128), blk>>>(y, w1, b1, h, FF, DM);
    sgemm_bias<false><<<dim3(DM / 128, SEQ / 128), blk>>>(h, w2, b2, tmp, DM, FF);
    ln_res_kernel<<<SEQ, blk>>>(y, tmp, g2, be2, out);
}